// round 9
// baseline (speedup 1.0000x reference)
#include <cuda_runtime.h>
#include <cuda_fp16.h>
#include <cstdint>

// Model_53283364274775 on GB300 (plain sm_103 PTX target -> no tcgen05):
// single-pass fp16 mma.sync. R9: in-register epilogue-2 (bias+lrelu+dot with
// shuffle reduce + 2KB spart buffer) replaces the 68KB D2 smem round-trip.

#define B_   8192
#define N_   32
#define TOT  (B_ * N_)          // 262144 = 2^18
#define SLOPE 0.01f

__device__ int   g_pos[3];
__device__ int   g_perm[3 * TOT];
__device__ float g_ui[B_ * 64];
// Pre-swizzled fp16 W0^T images: relations 0..2 = AO, 3 = UI. 32KB each.
__device__ float4 g_wimg[4 * 2048];
// W1 in direct mma B-fragment layout: [rel][wn][kk][lane] uint4
__device__ uint4 g_w1frag[4 * 1024];

__device__ __forceinline__ float lrelu(float x) { return x >= 0.f ? x : SLOPE * x; }

__device__ __forceinline__ uint32_t smem_to_u32(const void* p) {
    uint32_t a;
    asm("{ .reg .u64 t; cvta.to.shared.u64 t, %1; cvt.u32.u64 %0, t; }"
        : "=r"(a) : "l"(p));
    return a;
}
__device__ __forceinline__ void ldsm_x4(uint32_t& r0, uint32_t& r1,
                                        uint32_t& r2, uint32_t& r3, uint32_t addr) {
    asm volatile("ldmatrix.sync.aligned.m8n8.x4.shared.b16 {%0,%1,%2,%3}, [%4];"
        : "=r"(r0), "=r"(r1), "=r"(r2), "=r"(r3) : "r"(addr));
}
__device__ __forceinline__ void mma_f16(float* d, const uint32_t* a4,
                                        uint32_t b0, uint32_t b1) {
    asm volatile("mma.sync.aligned.m16n8k16.row.col.f32.f16.f16.f32 "
        "{%0,%1,%2,%3}, {%4,%5,%6,%7}, {%8,%9}, {%0,%1,%2,%3};"
        : "+f"(d[0]), "+f"(d[1]), "+f"(d[2]), "+f"(d[3])
        : "r"(a4[0]), "r"(a4[1]), "r"(a4[2]), "r"(a4[3]), "r"(b0), "r"(b1));
}
// 256B rows of fp16, XOR swizzle on 16B chunks: conflict-free ldmatrix
__device__ __forceinline__ uint32_t sw_off(int row, int chunk16) {
    return (uint32_t)(row * 256 + ((chunk16 ^ (row & 7)) << 4));
}
__device__ __forceinline__ uint32_t pack2h(float f0, float f1) {
    return (uint32_t)__half_as_ushort(__float2half_rn(f0)) |
           ((uint32_t)__half_as_ushort(__float2half_rn(f1)) << 16);
}

// smem layout (bytes):
// b0 @0 (512) | b1 @512 (256) | spart @768 (2048) | X1 @3072 (32K)
// | W0 @35840 (32K) | X2 @68608 (32K, AO only)
#define OFF_B0   0
#define OFF_B1   512
#define OFF_SP   768
#define OFF_X1   3072
#define OFF_W0   35840
#define OFF_X2   68608
#define SM_UI    68608
#define SM_AO    101376

// ======================= prep_w (+ g_pos init) =============================
__global__ void prep_w_kernel(const float* __restrict__ aoW0,
                              const float* __restrict__ aoW1,
                              const float* __restrict__ uiW0,
                              const float* __restrict__ uiW1) {
    int idx = blockIdx.x * blockDim.x + threadIdx.x;   // 0..49151
    if (blockIdx.x == 0 && threadIdx.x < 3)
        g_pos[threadIdx.x] = threadIdx.x * TOT;

    if (idx < 32768) {                 // W0^T smem image: 4 rel x 8192 (k2, n)
        int r = idx >> 13, p = idx & 8191;
        int k2 = p >> 7, n = p & 127;
        const float* W = (r < 3) ? (aoW0 + r * 16384) : uiW0;
        uint32_t hi = pack2h(W[(2 * k2) * 128 + n], W[(2 * k2 + 1) * 128 + n]);
        uint32_t off = sw_off(n, k2 >> 2) + (k2 & 3) * 4;
        *(uint32_t*)((uint8_t*)g_wimg + (size_t)r * 32768 + off) = hi;
    } else if (idx < 49152) {          // W1 fragment layout: 4 rel x 4096 words
        int t = idx - 32768;
        int r = t >> 12, q = t & 4095;
        int w    = q & 3;
        int lane = (q >> 2) & 31;
        int kk   = (q >> 7) & 7;
        int wn   = (q >> 10) & 3;
        const float* W = (r < 3) ? (aoW1 + r * 8192) : uiW1;
        int n = wn * 16 + (w >> 1) * 8 + (lane >> 2);
        int k = kk * 16 + (lane & 3) * 2 + (w & 1) * 8;
        uint32_t v = pack2h(W[k * 64 + n], W[(k + 1) * 64 + n]);
        ((uint32_t*)g_w1frag)[((size_t)r * 1024 + (wn * 8 + kk) * 32 + lane) * 4 + w] = v;
    }
}

// ======================= shared mma machinery ==============================
// GEMM1: D = X @ W0^T (W0 smem @OFF_W0), H=lrelu(D+b0) back into X region.
// GEMM2: acc2 = H @ W1^T, W1 B-fragments direct from gmem.
__device__ __forceinline__ void two_layer_mma(
    char* smem, uint32_t smem_base, int rel, int lane, int wm, int wn,
    uint32_t xoff, float (&acc2)[4][2][4])
{
    const float* sb0 = (const float*)(smem + OFF_B0);

    float acc[4][4][4];
    #pragma unroll
    for (int i = 0; i < 4; i++)
        #pragma unroll
        for (int j = 0; j < 4; j++)
            #pragma unroll
            for (int q = 0; q < 4; q++) acc[i][j][q] = 0.f;

    {
        const uint32_t Ab = smem_base + xoff;
        const uint32_t Bb = smem_base + OFF_W0;
        #pragma unroll
        for (int kk = 0; kk < 8; kk++) {
            const int chunk = kk * 2 + (lane >> 4);
            uint32_t af[4][4];
            #pragma unroll
            for (int i = 0; i < 4; i++) {
                int row = wm * 64 + i * 16 + (lane & 15);
                ldsm_x4(af[i][0], af[i][1], af[i][2], af[i][3],
                        Ab + sw_off(row, chunk));
            }
            uint32_t bf[4][2];
            #pragma unroll
            for (int h = 0; h < 2; h++) {
                int nrow = wn * 32 + h * 16 + (lane & 7) + ((lane >> 3) & 1) * 8;
                uint32_t r0, r1, r2, r3;
                ldsm_x4(r0, r1, r2, r3, Bb + sw_off(nrow, chunk));
                bf[h * 2][0] = r0; bf[h * 2][1] = r2;
                bf[h * 2 + 1][0] = r1; bf[h * 2 + 1][1] = r3;
            }
            #pragma unroll
            for (int i = 0; i < 4; i++)
                #pragma unroll
                for (int j = 0; j < 4; j++)
                    mma_f16(acc[i][j], af[i], bf[j][0], bf[j][1]);
        }
    }
    __syncthreads();

    // epilogue1: H = lrelu(D + b0) -> fp16 into X region
    #pragma unroll
    for (int i = 0; i < 4; i++) {
        int row0 = wm * 64 + i * 16 + (lane >> 2);
        #pragma unroll
        for (int j = 0; j < 4; j++) {
            int col = wn * 32 + j * 8 + 2 * (lane & 3);
            float bv0 = sb0[col], bv1 = sb0[col + 1];
            uint32_t h0 = pack2h(lrelu(acc[i][j][0] + bv0), lrelu(acc[i][j][1] + bv1));
            uint32_t h1 = pack2h(lrelu(acc[i][j][2] + bv0), lrelu(acc[i][j][3] + bv1));
            uint32_t o0 = sw_off(row0, col >> 3) + ((2 * col) & 15);
            uint32_t o1 = sw_off(row0 + 8, col >> 3) + ((2 * col) & 15);
            *(uint32_t*)(smem + xoff + o0) = h0;
            *(uint32_t*)(smem + xoff + o1) = h1;
        }
    }

    // W1 fragments: 8 coalesced uint4 per lane (L2-hot)
    uint4 w1f[8];
    {
        const uint4* wp = g_w1frag + (size_t)rel * 1024 + wn * 256 + lane;
        #pragma unroll
        for (int kk = 0; kk < 8; kk++) w1f[kk] = wp[kk * 32];
    }
    __syncthreads();

    #pragma unroll
    for (int i = 0; i < 4; i++)
        #pragma unroll
        for (int j = 0; j < 2; j++)
            #pragma unroll
            for (int q = 0; q < 4; q++) acc2[i][j][q] = 0.f;

    {
        const uint32_t Ab = smem_base + xoff;
        #pragma unroll
        for (int kk = 0; kk < 8; kk++) {
            const int chunk = kk * 2 + (lane >> 4);
            uint32_t af[4][4];
            #pragma unroll
            for (int i = 0; i < 4; i++) {
                int row = wm * 64 + i * 16 + (lane & 15);
                ldsm_x4(af[i][0], af[i][1], af[i][2], af[i][3],
                        Ab + sw_off(row, chunk));
            }
            #pragma unroll
            for (int i = 0; i < 4; i++) {
                mma_f16(acc2[i][0], af[i], w1f[kk].x, w1f[kk].y);
                mma_f16(acc2[i][1], af[i], w1f[kk].z, w1f[kk].w);
            }
        }
    }
}

__device__ __forceinline__ void load_weights(char* smem, int r, int tid,
                                             const float* b0, const float* b1) {
    const float4* wsrc = g_wimg + (size_t)r * 2048;
    float4* wdst = (float4*)(smem + OFF_W0);
    #pragma unroll 4
    for (int idx = tid; idx < 2048; idx += 256) wdst[idx] = wsrc[idx];
    if (tid < 128) ((float*)(smem + OFF_B0))[tid] = b0[tid];
    if (tid < 64)  ((float*)(smem + OFF_B1))[tid] = b1[tid];
}

// ======================= UI branch + scatter (fused) =======================
__global__ void __launch_bounds__(256, 2) ui_scatter_kernel(
    const float* __restrict__ u, const float* __restrict__ iv,
    const float* __restrict__ b0, const float* __restrict__ b1,
    const int* __restrict__ s_raw)
{
    extern __shared__ char smem[];
    const int tid = threadIdx.x;

    if (blockIdx.x >= 64) {
        // ---- scatter path (warp-aggregated bucket sort) ----
        __shared__ int sIs64;
        if (tid == 0) {
            int nz = 0;
            #pragma unroll
            for (int i = 1; i < 256; i += 2) nz |= s_raw[i];
            sIs64 = (nz == 0) ? 1 : 0;
        }
        __syncthreads();
        int idx = (blockIdx.x - 64) * 256 + tid;
        int lane = tid & 31;
        int r = sIs64 ? s_raw[2 * idx] : s_raw[idx];
        unsigned m0 = __ballot_sync(0xffffffffu, r == 0);
        unsigned m1 = __ballot_sync(0xffffffffu, r == 1);
        unsigned mine = (r == 0) ? m0 : (r == 1) ? m1 : ~(m0 | m1);
        int leader = __ffs(mine) - 1;
        int base = 0;
        if (lane == leader) base = atomicAdd(&g_pos[r], __popc(mine));
        base = __shfl_sync(0xffffffffu, base, leader);
        g_perm[base + __popc(mine & ((1u << lane) - 1u))] = idx;
        return;
    }

    // ---- UI path ----
    const uint32_t smem_base = smem_to_u32(smem);
    const int lane = tid & 31;
    const int wm = (tid >> 5) & 1;
    const int wn = tid >> 6;
    const int rowbase = blockIdx.x * 128;

    load_weights(smem, 3, tid, b0, b1);
    {
        const int xrow = tid >> 1;
        const int half = tid & 1;
        const float* src = (half ? iv : u) + (size_t)(rowbase + xrow) * 64;
        #pragma unroll
        for (int j = 0; j < 8; j++) {
            float4 v0 = ((const float4*)src)[2 * j];
            float4 v1 = ((const float4*)src)[2 * j + 1];
            uint32_t off = sw_off(xrow, half * 8 + j);
            *(uint4*)(smem + OFF_X1 + off) = make_uint4(
                pack2h(v0.x, v0.y), pack2h(v0.z, v0.w),
                pack2h(v1.x, v1.y), pack2h(v1.z, v1.w));
        }
    }
    __syncthreads();

    float acc2[4][2][4];
    two_layer_mma(smem, smem_base, 3, lane, wm, wn, OFF_X1, acc2);

    // epilogue: g_ui = lrelu(D2 + b1) straight from fragments
    const float* sb1 = (const float*)(smem + OFF_B1);
    #pragma unroll
    for (int i = 0; i < 4; i++) {
        int row0 = wm * 64 + i * 16 + (lane >> 2);
        #pragma unroll
        for (int j = 0; j < 2; j++) {
            int col = wn * 16 + j * 8 + 2 * (lane & 3);
            float bv0 = sb1[col], bv1 = sb1[col + 1];
            *(float2*)&g_ui[(size_t)(rowbase + row0) * 64 + col] =
                make_float2(lrelu(acc2[i][j][0] + bv0), lrelu(acc2[i][j][1] + bv1));
            *(float2*)&g_ui[(size_t)(rowbase + row0 + 8) * 64 + col] =
                make_float2(lrelu(acc2[i][j][2] + bv0), lrelu(acc2[i][j][3] + bv1));
        }
    }
}

// ======================= AO branch: 256 rows per CTA =======================
__global__ void __launch_bounds__(256, 2) ao_mma_kernel(
    const float* __restrict__ a, const float* __restrict__ o,
    const float* __restrict__ b0, const float* __restrict__ b1,
    float* __restrict__ out)
{
    extern __shared__ char smem[];
    const uint32_t smem_base = smem_to_u32(smem);
    const int tid = threadIdx.x;
    const int lane = tid & 31;
    const int wm = (tid >> 5) & 1;
    const int wn = tid >> 6;
    const int slotbase = blockIdx.x * 256;      // absolute in [0, 3*TOT)
    const int r = slotbase >> 18;               // TOT = 2^18
    const int local = slotbase & (TOT - 1);
    const int count = g_pos[r] - r * TOT;
    if (local >= count) return;
    const int nvalid = min(256, count - local);

    load_weights(smem, r, tid, b0 + r * 128, b1 + r * 64);

    // gather X for both blocks: thread = half a row of each block
    {
        const int xrow = tid >> 1;
        const int half = tid & 1;
        #pragma unroll
        for (int bi = 0; bi < 2; bi++) {
            uint32_t xoff = bi ? OFF_X2 : OFF_X1;
            if (bi * 128 + xrow < nvalid) {
                const int grow = g_perm[slotbase + bi * 128 + xrow];
                const float* src = (half ? o : a) + (size_t)grow * 64;
                #pragma unroll
                for (int j = 0; j < 8; j++) {
                    float4 v0 = ((const float4*)src)[2 * j];
                    float4 v1 = ((const float4*)src)[2 * j + 1];
                    uint32_t off = sw_off(xrow, half * 8 + j);
                    *(uint4*)(smem + xoff + off) = make_uint4(
                        pack2h(v0.x, v0.y), pack2h(v0.z, v0.w),
                        pack2h(v1.x, v1.y), pack2h(v1.z, v1.w));
                }
            } else {
                #pragma unroll
                for (int j = 0; j < 8; j++)
                    *(uint4*)(smem + xoff + sw_off(xrow, half * 8 + j)) =
                        make_uint4(0, 0, 0, 0);
            }
        }
    }
    __syncthreads();

    const float* sb1 = (const float*)(smem + OFF_B1);
    float* spart = (float*)(smem + OFF_SP);      // [128 rows][4 wn]

    #pragma unroll 1
    for (int bi = 0; bi < 2; bi++) {
        if (bi * 128 >= nvalid) break;
        const uint32_t xoff = bi ? OFF_X2 : OFF_X1;
        float acc2[4][2][4];
        two_layer_mma(smem, smem_base, r, lane, wm, wn, xoff, acc2);

        // ---- in-register epilogue2: bias+lrelu+dot(ui), shuffle reduce ----
        // thread's 4 cols: c0, c0+1 (j=0), c0+8, c0+9 (j=1)
        const int c0 = wn * 16 + 2 * (lane & 3);
        const float b1c0 = sb1[c0],     b1c1 = sb1[c0 + 1];
        const float b1c8 = sb1[c0 + 8], b1c9 = sb1[c0 + 9];
        #pragma unroll
        for (int i = 0; i < 4; i++) {
            #pragma unroll
            for (int half = 0; half < 2; half++) {
                int row = wm * 64 + i * 16 + (lane >> 2) + half * 8;
                float p = 0.f;
                if (bi * 128 + row < nvalid) {
                    int grow = g_perm[slotbase + bi * 128 + row];
                    const float* uir = g_ui + (size_t)(grow >> 5) * 64;
                    float2 ua = *(const float2*)(uir + c0);
                    float2 ub = *(const float2*)(uir + c0 + 8);
                    p = lrelu(acc2[i][0][half * 2 + 0] + b1c0) * ua.x
                      + lrelu(acc2[i][0][half * 2 + 1] + b1c1) * ua.y
                      + lrelu(acc2[i][1][half * 2 + 0] + b1c8) * ub.x
                      + lrelu(acc2[i][1][half * 2 + 1] + b1c9) * ub.y;
                }
                p += __shfl_xor_sync(0xffffffffu, p, 1);
                p += __shfl_xor_sync(0xffffffffu, p, 2);
                if ((lane & 3) == 0) spart[row * 4 + wn] = p;
            }
        }
        __syncthreads();

        if (tid < 128 && bi * 128 + tid < nvalid) {
            int grow = g_perm[slotbase + bi * 128 + tid];
            const float* sp = spart + tid * 4;
            out[grow] = (sp[0] + sp[1]) + (sp[2] + sp[3]);
        }
        // no trailing barrier needed: next block's spart writes are ordered
        // behind two_layer_mma's internal __syncthreads barriers.
    }
}

// ===========================================================================
extern "C" void kernel_launch(void* const* d_in, const int* in_sizes, int n_in,
                              void* d_out, int out_size) {
    const float* u    = (const float*)d_in[0];
    const float* iv   = (const float*)d_in[1];
    const float* a    = (const float*)d_in[2];
    const float* o    = (const float*)d_in[3];
    const int*   s    = (const int*)  d_in[4];
    const float* aoW0 = (const float*)d_in[5];
    const float* aob0 = (const float*)d_in[6];
    const float* aoW1 = (const float*)d_in[7];
    const float* aob1 = (const float*)d_in[8];
    const float* uiW0 = (const float*)d_in[9];
    const float* uib0 = (const float*)d_in[10];
    const float* uiW1 = (const float*)d_in[11];
    const float* uib1 = (const float*)d_in[12];
    float* out = (float*)d_out;

    cudaFuncSetAttribute((const void*)ui_scatter_kernel,
                         cudaFuncAttributeMaxDynamicSharedMemorySize, SM_UI);
    cudaFuncSetAttribute((const void*)ao_mma_kernel,
                         cudaFuncAttributeMaxDynamicSharedMemorySize, SM_AO);

    prep_w_kernel<<<192, 256>>>(aoW0, aoW1, uiW0, uiW1);
    ui_scatter_kernel<<<64 + TOT / 256, 256, SM_UI>>>(u, iv, uib0, uib1, s);
    ao_mma_kernel<<<3 * TOT / 256, 256, SM_AO>>>(a, o, aob0, aob1, out);
}

// round 10
// speedup vs baseline: 1.1350x; 1.1350x over previous
#include <cuda_runtime.h>
#include <cuda_fp16.h>
#include <cstdint>

// Model_53283364274775 on GB300 (plain sm_103 PTX target -> no tcgen05):
// single-pass fp16 mma.sync. R10 = R8 structure (smem D2 epilogue) +
// 2KB X1 pad (no W0 clobber/reload) + compact AO grid (1027 CTAs).

#define B_   8192
#define N_   32
#define TOT  (B_ * N_)          // 262144 = 2^18
#define SLOPE 0.01f

__device__ int   g_pos[3];
__device__ int   g_perm[3 * TOT];
__device__ float g_ui[B_ * 64];
// Pre-swizzled fp16 W0^T images: relations 0..2 = AO, 3 = UI. 32KB each.
__device__ float4 g_wimg[4 * 2048];
// W1 in direct mma B-fragment layout: [rel][wn][kk][lane] uint4
__device__ uint4 g_w1frag[4 * 1024];

__device__ __forceinline__ float lrelu(float x) { return x >= 0.f ? x : SLOPE * x; }

__device__ __forceinline__ uint32_t smem_to_u32(const void* p) {
    uint32_t a;
    asm("{ .reg .u64 t; cvta.to.shared.u64 t, %1; cvt.u32.u64 %0, t; }"
        : "=r"(a) : "l"(p));
    return a;
}
__device__ __forceinline__ void ldsm_x4(uint32_t& r0, uint32_t& r1,
                                        uint32_t& r2, uint32_t& r3, uint32_t addr) {
    asm volatile("ldmatrix.sync.aligned.m8n8.x4.shared.b16 {%0,%1,%2,%3}, [%4];"
        : "=r"(r0), "=r"(r1), "=r"(r2), "=r"(r3) : "r"(addr));
}
__device__ __forceinline__ void mma_f16(float* d, const uint32_t* a4,
                                        uint32_t b0, uint32_t b1) {
    asm volatile("mma.sync.aligned.m16n8k16.row.col.f32.f16.f16.f32 "
        "{%0,%1,%2,%3}, {%4,%5,%6,%7}, {%8,%9}, {%0,%1,%2,%3};"
        : "+f"(d[0]), "+f"(d[1]), "+f"(d[2]), "+f"(d[3])
        : "r"(a4[0]), "r"(a4[1]), "r"(a4[2]), "r"(a4[3]), "r"(b0), "r"(b1));
}
// 256B rows of fp16, XOR swizzle on 16B chunks: conflict-free ldmatrix
__device__ __forceinline__ uint32_t sw_off(int row, int chunk16) {
    return (uint32_t)(row * 256 + ((chunk16 ^ (row & 7)) << 4));
}
__device__ __forceinline__ uint32_t pack2h(float f0, float f1) {
    return (uint32_t)__half_as_ushort(__float2half_rn(f0)) |
           ((uint32_t)__half_as_ushort(__float2half_rn(f1)) << 16);
}

// smem layout (bytes): b0 @0 (512) | b1 @512 (256) | X1 @1024 (32K)
// | pad 2K | W0 @35840 (32K) | X2 @68608 (32K, AO only)
// D2 staging: block0 -> @X1 (fits X1+pad = 34816 exactly);
//             block1 -> @W0 (W0 dead; overruns 2KB into dead X2 head)
#define OFF_B0   0
#define OFF_B1   512
#define OFF_X1   1024
#define OFF_W0   35840
#define OFF_X2   68608
#define SM_UI    68608
#define SM_AO    101376

// ======================= prep_w (+ g_pos init) =============================
__global__ void prep_w_kernel(const float* __restrict__ aoW0,
                              const float* __restrict__ aoW1,
                              const float* __restrict__ uiW0,
                              const float* __restrict__ uiW1) {
    int idx = blockIdx.x * blockDim.x + threadIdx.x;   // 0..49151
    if (blockIdx.x == 0 && threadIdx.x < 3)
        g_pos[threadIdx.x] = threadIdx.x * TOT;

    if (idx < 32768) {                 // W0^T smem image: 4 rel x 8192 (k2, n)
        int r = idx >> 13, p = idx & 8191;
        int k2 = p >> 7, n = p & 127;
        const float* W = (r < 3) ? (aoW0 + r * 16384) : uiW0;
        uint32_t hi = pack2h(W[(2 * k2) * 128 + n], W[(2 * k2 + 1) * 128 + n]);
        uint32_t off = sw_off(n, k2 >> 2) + (k2 & 3) * 4;
        *(uint32_t*)((uint8_t*)g_wimg + (size_t)r * 32768 + off) = hi;
    } else if (idx < 49152) {          // W1 fragment layout: 4 rel x 4096 words
        int t = idx - 32768;
        int r = t >> 12, q = t & 4095;
        int w    = q & 3;
        int lane = (q >> 2) & 31;
        int kk   = (q >> 7) & 7;
        int wn   = (q >> 10) & 3;
        const float* W = (r < 3) ? (aoW1 + r * 8192) : uiW1;
        int n = wn * 16 + (w >> 1) * 8 + (lane >> 2);
        int k = kk * 16 + (lane & 3) * 2 + (w & 1) * 8;
        uint32_t v = pack2h(W[k * 64 + n], W[(k + 1) * 64 + n]);
        ((uint32_t*)g_w1frag)[((size_t)r * 1024 + (wn * 8 + kk) * 32 + lane) * 4 + w] = v;
    }
}

// ======================= shared mma machinery ==============================
// GEMM1: D = X @ W0^T (W0 smem @OFF_W0), H=lrelu(D+b0) back into X region.
// GEMM2: acc2 = H @ W1^T, W1 B-fragments direct from gmem.
__device__ __forceinline__ void two_layer_mma(
    char* smem, uint32_t smem_base, int rel, int lane, int wm, int wn,
    uint32_t xoff, float (&acc2)[4][2][4])
{
    const float* sb0 = (const float*)(smem + OFF_B0);

    float acc[4][4][4];
    #pragma unroll
    for (int i = 0; i < 4; i++)
        #pragma unroll
        for (int j = 0; j < 4; j++)
            #pragma unroll
            for (int q = 0; q < 4; q++) acc[i][j][q] = 0.f;

    {
        const uint32_t Ab = smem_base + xoff;
        const uint32_t Bb = smem_base + OFF_W0;
        #pragma unroll
        for (int kk = 0; kk < 8; kk++) {
            const int chunk = kk * 2 + (lane >> 4);
            uint32_t af[4][4];
            #pragma unroll
            for (int i = 0; i < 4; i++) {
                int row = wm * 64 + i * 16 + (lane & 15);
                ldsm_x4(af[i][0], af[i][1], af[i][2], af[i][3],
                        Ab + sw_off(row, chunk));
            }
            uint32_t bf[4][2];
            #pragma unroll
            for (int h = 0; h < 2; h++) {
                int nrow = wn * 32 + h * 16 + (lane & 7) + ((lane >> 3) & 1) * 8;
                uint32_t r0, r1, r2, r3;
                ldsm_x4(r0, r1, r2, r3, Bb + sw_off(nrow, chunk));
                bf[h * 2][0] = r0; bf[h * 2][1] = r2;
                bf[h * 2 + 1][0] = r1; bf[h * 2 + 1][1] = r3;
            }
            #pragma unroll
            for (int i = 0; i < 4; i++)
                #pragma unroll
                for (int j = 0; j < 4; j++)
                    mma_f16(acc[i][j], af[i], bf[j][0], bf[j][1]);
        }
    }
    __syncthreads();

    // epilogue1: H = lrelu(D + b0) -> fp16 into X region
    #pragma unroll
    for (int i = 0; i < 4; i++) {
        int row0 = wm * 64 + i * 16 + (lane >> 2);
        #pragma unroll
        for (int j = 0; j < 4; j++) {
            int col = wn * 32 + j * 8 + 2 * (lane & 3);
            float bv0 = sb0[col], bv1 = sb0[col + 1];
            uint32_t h0 = pack2h(lrelu(acc[i][j][0] + bv0), lrelu(acc[i][j][1] + bv1));
            uint32_t h1 = pack2h(lrelu(acc[i][j][2] + bv0), lrelu(acc[i][j][3] + bv1));
            uint32_t o0 = sw_off(row0, col >> 3) + ((2 * col) & 15);
            uint32_t o1 = sw_off(row0 + 8, col >> 3) + ((2 * col) & 15);
            *(uint32_t*)(smem + xoff + o0) = h0;
            *(uint32_t*)(smem + xoff + o1) = h1;
        }
    }

    // W1 fragments: 8 coalesced uint4 per lane (L2-hot)
    uint4 w1f[8];
    {
        const uint4* wp = g_w1frag + (size_t)rel * 1024 + wn * 256 + lane;
        #pragma unroll
        for (int kk = 0; kk < 8; kk++) w1f[kk] = wp[kk * 32];
    }
    __syncthreads();

    #pragma unroll
    for (int i = 0; i < 4; i++)
        #pragma unroll
        for (int j = 0; j < 2; j++)
            #pragma unroll
            for (int q = 0; q < 4; q++) acc2[i][j][q] = 0.f;

    {
        const uint32_t Ab = smem_base + xoff;
        #pragma unroll
        for (int kk = 0; kk < 8; kk++) {
            const int chunk = kk * 2 + (lane >> 4);
            uint32_t af[4][4];
            #pragma unroll
            for (int i = 0; i < 4; i++) {
                int row = wm * 64 + i * 16 + (lane & 15);
                ldsm_x4(af[i][0], af[i][1], af[i][2], af[i][3],
                        Ab + sw_off(row, chunk));
            }
            #pragma unroll
            for (int i = 0; i < 4; i++) {
                mma_f16(acc2[i][0], af[i], w1f[kk].x, w1f[kk].y);
                mma_f16(acc2[i][1], af[i], w1f[kk].z, w1f[kk].w);
            }
        }
    }
}

__device__ __forceinline__ void load_weights(char* smem, int r, int tid,
                                             const float* b0, const float* b1) {
    const float4* wsrc = g_wimg + (size_t)r * 2048;
    float4* wdst = (float4*)(smem + OFF_W0);
    #pragma unroll 4
    for (int idx = tid; idx < 2048; idx += 256) wdst[idx] = wsrc[idx];
    if (tid < 128) ((float*)(smem + OFF_B0))[tid] = b0[tid];
    if (tid < 64)  ((float*)(smem + OFF_B1))[tid] = b1[tid];
}

// ======================= UI branch + scatter (fused) =======================
__global__ void __launch_bounds__(256, 2) ui_scatter_kernel(
    const float* __restrict__ u, const float* __restrict__ iv,
    const float* __restrict__ b0, const float* __restrict__ b1,
    const int* __restrict__ s_raw)
{
    extern __shared__ char smem[];
    const int tid = threadIdx.x;

    if (blockIdx.x >= 64) {
        // ---- scatter path (warp-aggregated bucket sort) ----
        __shared__ int sIs64;
        if (tid == 0) {
            int nz = 0;
            #pragma unroll
            for (int i = 1; i < 256; i += 2) nz |= s_raw[i];
            sIs64 = (nz == 0) ? 1 : 0;
        }
        __syncthreads();
        int idx = (blockIdx.x - 64) * 256 + tid;
        int lane = tid & 31;
        int r = sIs64 ? s_raw[2 * idx] : s_raw[idx];
        unsigned m0 = __ballot_sync(0xffffffffu, r == 0);
        unsigned m1 = __ballot_sync(0xffffffffu, r == 1);
        unsigned mine = (r == 0) ? m0 : (r == 1) ? m1 : ~(m0 | m1);
        int leader = __ffs(mine) - 1;
        int base = 0;
        if (lane == leader) base = atomicAdd(&g_pos[r], __popc(mine));
        base = __shfl_sync(0xffffffffu, base, leader);
        g_perm[base + __popc(mine & ((1u << lane) - 1u))] = idx;
        return;
    }

    // ---- UI path ----
    const uint32_t smem_base = smem_to_u32(smem);
    const int lane = tid & 31;
    const int wm = (tid >> 5) & 1;
    const int wn = tid >> 6;
    const int rowbase = blockIdx.x * 128;

    load_weights(smem, 3, tid, b0, b1);
    {
        const int xrow = tid >> 1;
        const int half = tid & 1;
        const float* src = (half ? iv : u) + (size_t)(rowbase + xrow) * 64;
        #pragma unroll
        for (int j = 0; j < 8; j++) {
            float4 v0 = ((const float4*)src)[2 * j];
            float4 v1 = ((const float4*)src)[2 * j + 1];
            uint32_t off = sw_off(xrow, half * 8 + j);
            *(uint4*)(smem + OFF_X1 + off) = make_uint4(
                pack2h(v0.x, v0.y), pack2h(v0.z, v0.w),
                pack2h(v1.x, v1.y), pack2h(v1.z, v1.w));
        }
    }
    __syncthreads();

    float acc2[4][2][4];
    two_layer_mma(smem, smem_base, 3, lane, wm, wn, OFF_X1, acc2);

    // epilogue: g_ui = lrelu(D2 + b1) straight from fragments
    const float* sb1 = (const float*)(smem + OFF_B1);
    #pragma unroll
    for (int i = 0; i < 4; i++) {
        int row0 = wm * 64 + i * 16 + (lane >> 2);
        #pragma unroll
        for (int j = 0; j < 2; j++) {
            int col = wn * 16 + j * 8 + 2 * (lane & 3);
            float bv0 = sb1[col], bv1 = sb1[col + 1];
            *(float2*)&g_ui[(size_t)(rowbase + row0) * 64 + col] =
                make_float2(lrelu(acc2[i][j][0] + bv0), lrelu(acc2[i][j][1] + bv1));
            *(float2*)&g_ui[(size_t)(rowbase + row0 + 8) * 64 + col] =
                make_float2(lrelu(acc2[i][j][2] + bv0), lrelu(acc2[i][j][3] + bv1));
        }
    }
}

// ======================= AO branch: 256 rows per CTA, compact grid =========
// grid = TOT/256 + 3 = 1027 CTAs; bucket mapping computed from g_pos.
__global__ void __launch_bounds__(256, 2) ao_mma_kernel(
    const float* __restrict__ a, const float* __restrict__ o,
    const float* __restrict__ b0, const float* __restrict__ b1,
    float* __restrict__ out)
{
    extern __shared__ char smem[];
    const uint32_t smem_base = smem_to_u32(smem);
    const int tid = threadIdx.x;
    const int lane = tid & 31;
    const int wm = (tid >> 5) & 1;
    const int wn = tid >> 6;

    // runtime bucket mapping
    const int c0 = g_pos[0];
    const int c1 = g_pos[1] - TOT;
    const int c2 = g_pos[2] - 2 * TOT;
    const int nct0 = (c0 + 255) >> 8;
    const int nct1 = (c1 + 255) >> 8;
    const int nct2 = (c2 + 255) >> 8;
    const int bid = blockIdx.x;
    if (bid >= nct0 + nct1 + nct2) return;
    int r, cbase, count;
    if (bid < nct0)              { r = 0; cbase = bid;               count = c0; }
    else if (bid < nct0 + nct1)  { r = 1; cbase = bid - nct0;        count = c1; }
    else                         { r = 2; cbase = bid - nct0 - nct1; count = c2; }
    const int local = cbase * 256;
    const int slotbase = r * TOT + local;
    const int nvalid = min(256, count - local);

    load_weights(smem, r, tid, b0 + r * 128, b1 + r * 64);

    // gather X for both blocks: thread = half a row of each block
    {
        const int xrow = tid >> 1;
        const int half = tid & 1;
        #pragma unroll
        for (int bi = 0; bi < 2; bi++) {
            uint32_t xoff = bi ? OFF_X2 : OFF_X1;
            if (bi * 128 + xrow < nvalid) {
                const int grow = g_perm[slotbase + bi * 128 + xrow];
                const float* src = (half ? o : a) + (size_t)grow * 64;
                #pragma unroll
                for (int j = 0; j < 8; j++) {
                    float4 v0 = ((const float4*)src)[2 * j];
                    float4 v1 = ((const float4*)src)[2 * j + 1];
                    uint32_t off = sw_off(xrow, half * 8 + j);
                    *(uint4*)(smem + xoff + off) = make_uint4(
                        pack2h(v0.x, v0.y), pack2h(v0.z, v0.w),
                        pack2h(v1.x, v1.y), pack2h(v1.z, v1.w));
                }
            } else {
                #pragma unroll
                for (int j = 0; j < 8; j++)
                    *(uint4*)(smem + xoff + sw_off(xrow, half * 8 + j)) =
                        make_uint4(0, 0, 0, 0);
            }
        }
    }
    __syncthreads();

    const float* sb1 = (const float*)(smem + OFF_B1);

    #pragma unroll 1
    for (int bi = 0; bi < 2; bi++) {
        if (bi * 128 >= nvalid) break;
        const uint32_t xoff = bi ? OFF_X2 : OFF_X1;
        float acc2[4][2][4];
        two_layer_mma(smem, smem_base, r, lane, wm, wn, xoff, acc2);
        __syncthreads();

        // epilogue2: stage D2 (stride 68), then bias+lrelu+dot(ui).
        // block0 -> @X1 (fits X1+pad exactly); block1 -> @W0 (dead).
        float* sD2 = (float*)(smem + (bi ? OFF_W0 : OFF_X1));
        #pragma unroll
        for (int i = 0; i < 4; i++) {
            int row0 = wm * 64 + i * 16 + (lane >> 2);
            #pragma unroll
            for (int j = 0; j < 2; j++) {
                int col = wn * 16 + j * 8 + 2 * (lane & 3);
                *(float2*)&sD2[row0 * 68 + col] =
                    make_float2(acc2[i][j][0], acc2[i][j][1]);
                *(float2*)&sD2[(row0 + 8) * 68 + col] =
                    make_float2(acc2[i][j][2], acc2[i][j][3]);
            }
        }
        __syncthreads();

        if (tid < 128 && bi * 128 + tid < nvalid) {
            int grow = g_perm[slotbase + bi * 128 + tid];
            const float4* uir = (const float4*)(g_ui + (size_t)(grow >> 5) * 64);
            const float* drow = sD2 + tid * 68;
            float sdot = 0.f;
            #pragma unroll
            for (int c4 = 0; c4 < 16; c4++) {
                float4 uv = uir[c4];
                float v0 = lrelu(drow[4 * c4 + 0] + sb1[4 * c4 + 0]);
                float v1 = lrelu(drow[4 * c4 + 1] + sb1[4 * c4 + 1]);
                float v2 = lrelu(drow[4 * c4 + 2] + sb1[4 * c4 + 2]);
                float v3 = lrelu(drow[4 * c4 + 3] + sb1[4 * c4 + 3]);
                sdot = fmaf(v0, uv.x, sdot); sdot = fmaf(v1, uv.y, sdot);
                sdot = fmaf(v2, uv.z, sdot); sdot = fmaf(v3, uv.w, sdot);
            }
            out[grow] = sdot;
        }
        __syncthreads();
    }
}

// ===========================================================================
extern "C" void kernel_launch(void* const* d_in, const int* in_sizes, int n_in,
                              void* d_out, int out_size) {
    const float* u    = (const float*)d_in[0];
    const float* iv   = (const float*)d_in[1];
    const float* a    = (const float*)d_in[2];
    const float* o    = (const float*)d_in[3];
    const int*   s    = (const int*)  d_in[4];
    const float* aoW0 = (const float*)d_in[5];
    const float* aob0 = (const float*)d_in[6];
    const float* aoW1 = (const float*)d_in[7];
    const float* aob1 = (const float*)d_in[8];
    const float* uiW0 = (const float*)d_in[9];
    const float* uib0 = (const float*)d_in[10];
    const float* uiW1 = (const float*)d_in[11];
    const float* uib1 = (const float*)d_in[12];
    float* out = (float*)d_out;

    cudaFuncSetAttribute((const void*)ui_scatter_kernel,
                         cudaFuncAttributeMaxDynamicSharedMemorySize, SM_UI);
    cudaFuncSetAttribute((const void*)ao_mma_kernel,
                         cudaFuncAttributeMaxDynamicSharedMemorySize, SM_AO);

    prep_w_kernel<<<192, 256>>>(aoW0, aoW1, uiW0, uiW1);
    ui_scatter_kernel<<<64 + TOT / 256, 256, SM_UI>>>(u, iv, uib0, uib1, s);
    ao_mma_kernel<<<TOT / 256 + 3, 256, SM_AO>>>(a, o, aob0, aob1, out);
}

// round 11
// speedup vs baseline: 1.1746x; 1.0349x over previous
#include <cuda_runtime.h>
#include <cuda_fp16.h>
#include <cstdint>

// Model_53283364274775 on GB300 (plain sm_103 PTX target -> no tcgen05):
// single-pass fp16 mma.sync. R11 = exact R8 structure (3072-CTA early-exit
// grid, smem D2 epilogue) + 2KB X1 pad so D2 staging never clobbers W0
// (deletes the W0 reload + one barrier). A/B vs R10's compact grid.

#define B_   8192
#define N_   32
#define TOT  (B_ * N_)          // 262144 = 2^18
#define SLOPE 0.01f

__device__ int   g_pos[3];
__device__ int   g_perm[3 * TOT];
__device__ float g_ui[B_ * 64];
// Pre-swizzled fp16 W0^T images: relations 0..2 = AO, 3 = UI. 32KB each.
__device__ float4 g_wimg[4 * 2048];
// W1 in direct mma B-fragment layout: [rel][wn][kk][lane] uint4
__device__ uint4 g_w1frag[4 * 1024];

__device__ __forceinline__ float lrelu(float x) { return x >= 0.f ? x : SLOPE * x; }

__device__ __forceinline__ uint32_t smem_to_u32(const void* p) {
    uint32_t a;
    asm("{ .reg .u64 t; cvta.to.shared.u64 t, %1; cvt.u32.u64 %0, t; }"
        : "=r"(a) : "l"(p));
    return a;
}
__device__ __forceinline__ void ldsm_x4(uint32_t& r0, uint32_t& r1,
                                        uint32_t& r2, uint32_t& r3, uint32_t addr) {
    asm volatile("ldmatrix.sync.aligned.m8n8.x4.shared.b16 {%0,%1,%2,%3}, [%4];"
        : "=r"(r0), "=r"(r1), "=r"(r2), "=r"(r3) : "r"(addr));
}
__device__ __forceinline__ void mma_f16(float* d, const uint32_t* a4,
                                        uint32_t b0, uint32_t b1) {
    asm volatile("mma.sync.aligned.m16n8k16.row.col.f32.f16.f16.f32 "
        "{%0,%1,%2,%3}, {%4,%5,%6,%7}, {%8,%9}, {%0,%1,%2,%3};"
        : "+f"(d[0]), "+f"(d[1]), "+f"(d[2]), "+f"(d[3])
        : "r"(a4[0]), "r"(a4[1]), "r"(a4[2]), "r"(a4[3]), "r"(b0), "r"(b1));
}
// 256B rows of fp16, XOR swizzle on 16B chunks: conflict-free ldmatrix
__device__ __forceinline__ uint32_t sw_off(int row, int chunk16) {
    return (uint32_t)(row * 256 + ((chunk16 ^ (row & 7)) << 4));
}
__device__ __forceinline__ uint32_t pack2h(float f0, float f1) {
    return (uint32_t)__half_as_ushort(__float2half_rn(f0)) |
           ((uint32_t)__half_as_ushort(__float2half_rn(f1)) << 16);
}

// smem layout (bytes): b0 @0 (512) | b1 @512 (256) | X1 @1024 (32K)
// | pad 2K | W0 @35840 (32K) | X2 @68608 (32K, AO only)
// D2 staging (34816B): block0 -> @X1 (fits X1+pad exactly);
//                      block1 -> @W0 (W0 dead; overruns 2KB into dead X2 head)
#define OFF_B0   0
#define OFF_B1   512
#define OFF_X1   1024
#define OFF_W0   35840
#define OFF_X2   68608
#define SM_UI    68608
#define SM_AO    101376

// ======================= prep_w (+ g_pos init) =============================
__global__ void prep_w_kernel(const float* __restrict__ aoW0,
                              const float* __restrict__ aoW1,
                              const float* __restrict__ uiW0,
                              const float* __restrict__ uiW1) {
    int idx = blockIdx.x * blockDim.x + threadIdx.x;   // 0..49151
    if (blockIdx.x == 0 && threadIdx.x < 3)
        g_pos[threadIdx.x] = threadIdx.x * TOT;

    if (idx < 32768) {                 // W0^T smem image: 4 rel x 8192 (k2, n)
        int r = idx >> 13, p = idx & 8191;
        int k2 = p >> 7, n = p & 127;
        const float* W = (r < 3) ? (aoW0 + r * 16384) : uiW0;
        uint32_t hi = pack2h(W[(2 * k2) * 128 + n], W[(2 * k2 + 1) * 128 + n]);
        uint32_t off = sw_off(n, k2 >> 2) + (k2 & 3) * 4;
        *(uint32_t*)((uint8_t*)g_wimg + (size_t)r * 32768 + off) = hi;
    } else if (idx < 49152) {          // W1 fragment layout: 4 rel x 4096 words
        int t = idx - 32768;
        int r = t >> 12, q = t & 4095;
        int w    = q & 3;
        int lane = (q >> 2) & 31;
        int kk   = (q >> 7) & 7;
        int wn   = (q >> 10) & 3;
        const float* W = (r < 3) ? (aoW1 + r * 8192) : uiW1;
        int n = wn * 16 + (w >> 1) * 8 + (lane >> 2);
        int k = kk * 16 + (lane & 3) * 2 + (w & 1) * 8;
        uint32_t v = pack2h(W[k * 64 + n], W[(k + 1) * 64 + n]);
        ((uint32_t*)g_w1frag)[((size_t)r * 1024 + (wn * 8 + kk) * 32 + lane) * 4 + w] = v;
    }
}

// ======================= shared mma machinery ==============================
// GEMM1: D = X @ W0^T (W0 smem @OFF_W0), H=lrelu(D+b0) back into X region.
// GEMM2: acc2 = H @ W1^T, W1 B-fragments direct from gmem.
__device__ __forceinline__ void two_layer_mma(
    char* smem, uint32_t smem_base, int rel, int lane, int wm, int wn,
    uint32_t xoff, float (&acc2)[4][2][4])
{
    const float* sb0 = (const float*)(smem + OFF_B0);

    float acc[4][4][4];
    #pragma unroll
    for (int i = 0; i < 4; i++)
        #pragma unroll
        for (int j = 0; j < 4; j++)
            #pragma unroll
            for (int q = 0; q < 4; q++) acc[i][j][q] = 0.f;

    {
        const uint32_t Ab = smem_base + xoff;
        const uint32_t Bb = smem_base + OFF_W0;
        #pragma unroll
        for (int kk = 0; kk < 8; kk++) {
            const int chunk = kk * 2 + (lane >> 4);
            uint32_t af[4][4];
            #pragma unroll
            for (int i = 0; i < 4; i++) {
                int row = wm * 64 + i * 16 + (lane & 15);
                ldsm_x4(af[i][0], af[i][1], af[i][2], af[i][3],
                        Ab + sw_off(row, chunk));
            }
            uint32_t bf[4][2];
            #pragma unroll
            for (int h = 0; h < 2; h++) {
                int nrow = wn * 32 + h * 16 + (lane & 7) + ((lane >> 3) & 1) * 8;
                uint32_t r0, r1, r2, r3;
                ldsm_x4(r0, r1, r2, r3, Bb + sw_off(nrow, chunk));
                bf[h * 2][0] = r0; bf[h * 2][1] = r2;
                bf[h * 2 + 1][0] = r1; bf[h * 2 + 1][1] = r3;
            }
            #pragma unroll
            for (int i = 0; i < 4; i++)
                #pragma unroll
                for (int j = 0; j < 4; j++)
                    mma_f16(acc[i][j], af[i], bf[j][0], bf[j][1]);
        }
    }
    __syncthreads();

    // epilogue1: H = lrelu(D + b0) -> fp16 into X region
    #pragma unroll
    for (int i = 0; i < 4; i++) {
        int row0 = wm * 64 + i * 16 + (lane >> 2);
        #pragma unroll
        for (int j = 0; j < 4; j++) {
            int col = wn * 32 + j * 8 + 2 * (lane & 3);
            float bv0 = sb0[col], bv1 = sb0[col + 1];
            uint32_t h0 = pack2h(lrelu(acc[i][j][0] + bv0), lrelu(acc[i][j][1] + bv1));
            uint32_t h1 = pack2h(lrelu(acc[i][j][2] + bv0), lrelu(acc[i][j][3] + bv1));
            uint32_t o0 = sw_off(row0, col >> 3) + ((2 * col) & 15);
            uint32_t o1 = sw_off(row0 + 8, col >> 3) + ((2 * col) & 15);
            *(uint32_t*)(smem + xoff + o0) = h0;
            *(uint32_t*)(smem + xoff + o1) = h1;
        }
    }

    // W1 fragments: 8 coalesced uint4 per lane (L2-hot)
    uint4 w1f[8];
    {
        const uint4* wp = g_w1frag + (size_t)rel * 1024 + wn * 256 + lane;
        #pragma unroll
        for (int kk = 0; kk < 8; kk++) w1f[kk] = wp[kk * 32];
    }
    __syncthreads();

    #pragma unroll
    for (int i = 0; i < 4; i++)
        #pragma unroll
        for (int j = 0; j < 2; j++)
            #pragma unroll
            for (int q = 0; q < 4; q++) acc2[i][j][q] = 0.f;

    {
        const uint32_t Ab = smem_base + xoff;
        #pragma unroll
        for (int kk = 0; kk < 8; kk++) {
            const int chunk = kk * 2 + (lane >> 4);
            uint32_t af[4][4];
            #pragma unroll
            for (int i = 0; i < 4; i++) {
                int row = wm * 64 + i * 16 + (lane & 15);
                ldsm_x4(af[i][0], af[i][1], af[i][2], af[i][3],
                        Ab + sw_off(row, chunk));
            }
            #pragma unroll
            for (int i = 0; i < 4; i++) {
                mma_f16(acc2[i][0], af[i], w1f[kk].x, w1f[kk].y);
                mma_f16(acc2[i][1], af[i], w1f[kk].z, w1f[kk].w);
            }
        }
    }
}

__device__ __forceinline__ void load_weights(char* smem, int r, int tid,
                                             const float* b0, const float* b1) {
    const float4* wsrc = g_wimg + (size_t)r * 2048;
    float4* wdst = (float4*)(smem + OFF_W0);
    #pragma unroll 4
    for (int idx = tid; idx < 2048; idx += 256) wdst[idx] = wsrc[idx];
    if (tid < 128) ((float*)(smem + OFF_B0))[tid] = b0[tid];
    if (tid < 64)  ((float*)(smem + OFF_B1))[tid] = b1[tid];
}

// ======================= UI branch + scatter (fused) =======================
__global__ void __launch_bounds__(256, 2) ui_scatter_kernel(
    const float* __restrict__ u, const float* __restrict__ iv,
    const float* __restrict__ b0, const float* __restrict__ b1,
    const int* __restrict__ s_raw)
{
    extern __shared__ char smem[];
    const int tid = threadIdx.x;

    if (blockIdx.x >= 64) {
        // ---- scatter path (warp-aggregated bucket sort) ----
        __shared__ int sIs64;
        if (tid == 0) {
            int nz = 0;
            #pragma unroll
            for (int i = 1; i < 256; i += 2) nz |= s_raw[i];
            sIs64 = (nz == 0) ? 1 : 0;
        }
        __syncthreads();
        int idx = (blockIdx.x - 64) * 256 + tid;
        int lane = tid & 31;
        int r = sIs64 ? s_raw[2 * idx] : s_raw[idx];
        unsigned m0 = __ballot_sync(0xffffffffu, r == 0);
        unsigned m1 = __ballot_sync(0xffffffffu, r == 1);
        unsigned mine = (r == 0) ? m0 : (r == 1) ? m1 : ~(m0 | m1);
        int leader = __ffs(mine) - 1;
        int base = 0;
        if (lane == leader) base = atomicAdd(&g_pos[r], __popc(mine));
        base = __shfl_sync(0xffffffffu, base, leader);
        g_perm[base + __popc(mine & ((1u << lane) - 1u))] = idx;
        return;
    }

    // ---- UI path ----
    const uint32_t smem_base = smem_to_u32(smem);
    const int lane = tid & 31;
    const int wm = (tid >> 5) & 1;
    const int wn = tid >> 6;
    const int rowbase = blockIdx.x * 128;

    load_weights(smem, 3, tid, b0, b1);
    {
        const int xrow = tid >> 1;
        const int half = tid & 1;
        const float* src = (half ? iv : u) + (size_t)(rowbase + xrow) * 64;
        #pragma unroll
        for (int j = 0; j < 8; j++) {
            float4 v0 = ((const float4*)src)[2 * j];
            float4 v1 = ((const float4*)src)[2 * j + 1];
            uint32_t off = sw_off(xrow, half * 8 + j);
            *(uint4*)(smem + OFF_X1 + off) = make_uint4(
                pack2h(v0.x, v0.y), pack2h(v0.z, v0.w),
                pack2h(v1.x, v1.y), pack2h(v1.z, v1.w));
        }
    }
    __syncthreads();

    float acc2[4][2][4];
    two_layer_mma(smem, smem_base, 3, lane, wm, wn, OFF_X1, acc2);

    // epilogue: g_ui = lrelu(D2 + b1) straight from fragments
    const float* sb1 = (const float*)(smem + OFF_B1);
    #pragma unroll
    for (int i = 0; i < 4; i++) {
        int row0 = wm * 64 + i * 16 + (lane >> 2);
        #pragma unroll
        for (int j = 0; j < 2; j++) {
            int col = wn * 16 + j * 8 + 2 * (lane & 3);
            float bv0 = sb1[col], bv1 = sb1[col + 1];
            *(float2*)&g_ui[(size_t)(rowbase + row0) * 64 + col] =
                make_float2(lrelu(acc2[i][j][0] + bv0), lrelu(acc2[i][j][1] + bv1));
            *(float2*)&g_ui[(size_t)(rowbase + row0 + 8) * 64 + col] =
                make_float2(lrelu(acc2[i][j][2] + bv0), lrelu(acc2[i][j][3] + bv1));
        }
    }
}

// ======================= AO branch: 256 rows per CTA =======================
// R8-style grid: 3*TOT/256 CTAs, empty tails exit immediately.
__global__ void __launch_bounds__(256, 2) ao_mma_kernel(
    const float* __restrict__ a, const float* __restrict__ o,
    const float* __restrict__ b0, const float* __restrict__ b1,
    float* __restrict__ out)
{
    extern __shared__ char smem[];
    const uint32_t smem_base = smem_to_u32(smem);
    const int tid = threadIdx.x;
    const int lane = tid & 31;
    const int wm = (tid >> 5) & 1;
    const int wn = tid >> 6;
    const int slotbase = blockIdx.x * 256;      // absolute in [0, 3*TOT)
    const int r = slotbase >> 18;               // TOT = 2^18
    const int local = slotbase & (TOT - 1);
    const int count = g_pos[r] - r * TOT;
    if (local >= count) return;
    const int nvalid = min(256, count - local);

    load_weights(smem, r, tid, b0 + r * 128, b1 + r * 64);

    // gather X for both blocks: thread = half a row of each block
    {
        const int xrow = tid >> 1;
        const int half = tid & 1;
        #pragma unroll
        for (int bi = 0; bi < 2; bi++) {
            uint32_t xoff = bi ? OFF_X2 : OFF_X1;
            if (bi * 128 + xrow < nvalid) {
                const int grow = g_perm[slotbase + bi * 128 + xrow];
                const float* src = (half ? o : a) + (size_t)grow * 64;
                #pragma unroll
                for (int j = 0; j < 8; j++) {
                    float4 v0 = ((const float4*)src)[2 * j];
                    float4 v1 = ((const float4*)src)[2 * j + 1];
                    uint32_t off = sw_off(xrow, half * 8 + j);
                    *(uint4*)(smem + xoff + off) = make_uint4(
                        pack2h(v0.x, v0.y), pack2h(v0.z, v0.w),
                        pack2h(v1.x, v1.y), pack2h(v1.z, v1.w));
                }
            } else {
                #pragma unroll
                for (int j = 0; j < 8; j++)
                    *(uint4*)(smem + xoff + sw_off(xrow, half * 8 + j)) =
                        make_uint4(0, 0, 0, 0);
            }
        }
    }
    __syncthreads();

    const float* sb1 = (const float*)(smem + OFF_B1);

    #pragma unroll 1
    for (int bi = 0; bi < 2; bi++) {
        if (bi * 128 >= nvalid) break;
        const uint32_t xoff = bi ? OFF_X2 : OFF_X1;
        float acc2[4][2][4];
        two_layer_mma(smem, smem_base, r, lane, wm, wn, xoff, acc2);
        __syncthreads();

        // epilogue2: stage D2 (stride 68), then bias+lrelu+dot(ui).
        // block0 -> @X1 (fits X1+pad exactly, W0 untouched); block1 -> @W0.
        float* sD2 = (float*)(smem + (bi ? OFF_W0 : OFF_X1));
        #pragma unroll
        for (int i = 0; i < 4; i++) {
            int row0 = wm * 64 + i * 16 + (lane >> 2);
            #pragma unroll
            for (int j = 0; j < 2; j++) {
                int col = wn * 16 + j * 8 + 2 * (lane & 3);
                *(float2*)&sD2[row0 * 68 + col] =
                    make_float2(acc2[i][j][0], acc2[i][j][1]);
                *(float2*)&sD2[(row0 + 8) * 68 + col] =
                    make_float2(acc2[i][j][2], acc2[i][j][3]);
            }
        }
        __syncthreads();

        if (tid < 128 && bi * 128 + tid < nvalid) {
            int grow = g_perm[slotbase + bi * 128 + tid];
            const float4* uir = (const float4*)(g_ui + (size_t)(grow >> 5) * 64);
            const float* drow = sD2 + tid * 68;
            float sdot = 0.f;
            #pragma unroll
            for (int c4 = 0; c4 < 16; c4++) {
                float4 uv = uir[c4];
                float v0 = lrelu(drow[4 * c4 + 0] + sb1[4 * c4 + 0]);
                float v1 = lrelu(drow[4 * c4 + 1] + sb1[4 * c4 + 1]);
                float v2 = lrelu(drow[4 * c4 + 2] + sb1[4 * c4 + 2]);
                float v3 = lrelu(drow[4 * c4 + 3] + sb1[4 * c4 + 3]);
                sdot = fmaf(v0, uv.x, sdot); sdot = fmaf(v1, uv.y, sdot);
                sdot = fmaf(v2, uv.z, sdot); sdot = fmaf(v3, uv.w, sdot);
            }
            out[grow] = sdot;
        }
        __syncthreads();
    }
}

// ===========================================================================
extern "C" void kernel_launch(void* const* d_in, const int* in_sizes, int n_in,
                              void* d_out, int out_size) {
    const float* u    = (const float*)d_in[0];
    const float* iv   = (const float*)d_in[1];
    const float* a    = (const float*)d_in[2];
    const float* o    = (const float*)d_in[3];
    const int*   s    = (const int*)  d_in[4];
    const float* aoW0 = (const float*)d_in[5];
    const float* aob0 = (const float*)d_in[6];
    const float* aoW1 = (const float*)d_in[7];
    const float* aob1 = (const float*)d_in[8];
    const float* uiW0 = (const float*)d_in[9];
    const float* uib0 = (const float*)d_in[10];
    const float* uiW1 = (const float*)d_in[11];
    const float* uib1 = (const float*)d_in[12];
    float* out = (float*)d_out;

    cudaFuncSetAttribute((const void*)ui_scatter_kernel,
                         cudaFuncAttributeMaxDynamicSharedMemorySize, SM_UI);
    cudaFuncSetAttribute((const void*)ao_mma_kernel,
                         cudaFuncAttributeMaxDynamicSharedMemorySize, SM_AO);

    prep_w_kernel<<<192, 256>>>(aoW0, aoW1, uiW0, uiW1);
    ui_scatter_kernel<<<64 + TOT / 256, 256, SM_UI>>>(u, iv, uib0, uib1, s);
    ao_mma_kernel<<<3 * TOT / 256, 256, SM_AO>>>(a, o, aob0, aob1, out);
}

// round 12
// speedup vs baseline: 1.1837x; 1.0078x over previous
#include <cuda_runtime.h>
#include <cuda_fp16.h>
#include <cstdint>

// Model_53283364274775 on GB300 (plain sm_103 PTX target -> no tcgen05):
// single-pass fp16 mma.sync. R12: all weights streamed as pre-baked mma
// B-fragments from gmem (L2-hot); W0 smem image deleted. GEMM1 warp grid
// 4x2 (m32n64, A-redundancy 2x), GEMM2 8x1 (m16n64, A-redundancy 1x).

#define B_   8192
#define N_   32
#define TOT  (B_ * N_)          // 262144 = 2^18
#define SLOPE 0.01f

__device__ int   g_pos[3];
__device__ int   g_perm[3 * TOT];
__device__ float g_ui[B_ * 64];
// W0 in mma B-fragment layout: [rel][wn1(2)][kk(8)][q(4)][lane] uint4 (32KB/rel)
__device__ uint4 g_w0frag[4 * 2 * 8 * 128];
// W1 in mma B-fragment layout: [rel][kk(8)][q(4)][lane] uint4 (16KB/rel)
__device__ uint4 g_w1frag[4 * 8 * 128];

__device__ __forceinline__ float lrelu(float x) { return x >= 0.f ? x : SLOPE * x; }

__device__ __forceinline__ uint32_t smem_to_u32(const void* p) {
    uint32_t a;
    asm("{ .reg .u64 t; cvta.to.shared.u64 t, %1; cvt.u32.u64 %0, t; }"
        : "=r"(a) : "l"(p));
    return a;
}
__device__ __forceinline__ void ldsm_x4(uint32_t& r0, uint32_t& r1,
                                        uint32_t& r2, uint32_t& r3, uint32_t addr) {
    asm volatile("ldmatrix.sync.aligned.m8n8.x4.shared.b16 {%0,%1,%2,%3}, [%4];"
        : "=r"(r0), "=r"(r1), "=r"(r2), "=r"(r3) : "r"(addr));
}
__device__ __forceinline__ void mma_f16(float* d, const uint32_t* a4,
                                        uint32_t b0, uint32_t b1) {
    asm volatile("mma.sync.aligned.m16n8k16.row.col.f32.f16.f16.f32 "
        "{%0,%1,%2,%3}, {%4,%5,%6,%7}, {%8,%9}, {%0,%1,%2,%3};"
        : "+f"(d[0]), "+f"(d[1]), "+f"(d[2]), "+f"(d[3])
        : "r"(a4[0]), "r"(a4[1]), "r"(a4[2]), "r"(a4[3]), "r"(b0), "r"(b1));
}
// 256B rows of fp16, XOR swizzle on 16B chunks: conflict-free ldmatrix
__device__ __forceinline__ uint32_t sw_off(int row, int chunk16) {
    return (uint32_t)(row * 256 + ((chunk16 ^ (row & 7)) << 4));
}
__device__ __forceinline__ uint32_t pack2h(float f0, float f1) {
    return (uint32_t)__half_as_ushort(__float2half_rn(f0)) |
           ((uint32_t)__half_as_ushort(__float2half_rn(f1)) << 16);
}

// smem layout (bytes): b0 @0 (512) | b1 @512 (256) | X1 @1024 (32K + 2K pad)
// | X2 @35840 (32K + 2K pad).  D2 staging (34816B) goes into X1 / X2 regions.
#define OFF_B0   0
#define OFF_B1   512
#define OFF_X1   1024
#define OFF_X2   35840
#define SM_UI    33792
#define SM_AO    70656

// ======================= prep_w (+ g_pos init) =============================
__global__ void prep_w_kernel(const float* __restrict__ aoW0,
                              const float* __restrict__ aoW1,
                              const float* __restrict__ uiW0,
                              const float* __restrict__ uiW1) {
    int idx = blockIdx.x * blockDim.x + threadIdx.x;   // 0..49151
    if (blockIdx.x == 0 && threadIdx.x < 3)
        g_pos[threadIdx.x] = threadIdx.x * TOT;

    if (idx < 32768) {
        // W0 fragments: word idx = (((r*2+wn1)*8+kk)*128 + q*32 + lane)*4 + w
        int r = idx >> 13, t = idx & 8191;
        int w    = t & 3;
        int lane = (t >> 2) & 31;
        int q    = (t >> 7) & 3;
        int kk   = (t >> 9) & 7;
        int wn1  = (t >> 12) & 1;
        const float* W = (r < 3) ? (aoW0 + r * 16384) : uiW0;
        int j = 2 * q + (w >> 1);
        int n = wn1 * 64 + j * 8 + (lane >> 2);
        int k = kk * 16 + (lane & 3) * 2 + (w & 1) * 8;
        uint32_t v = pack2h(W[k * 128 + n], W[(k + 1) * 128 + n]);
        ((uint32_t*)g_w0frag)[((((size_t)r * 2 + wn1) * 8 + kk) * 128 + q * 32 + lane) * 4 + w] = v;
    } else if (idx < 49152) {
        // W1 fragments: word idx = ((r*8+kk)*128 + q*32 + lane)*4 + w
        int t2 = idx - 32768;
        int r = t2 >> 12, t = t2 & 4095;
        int w    = t & 3;
        int lane = (t >> 2) & 31;
        int q    = (t >> 7) & 3;
        int kk   = (t >> 9) & 7;
        const float* W = (r < 3) ? (aoW1 + r * 8192) : uiW1;
        int j = 2 * q + (w >> 1);
        int n = j * 8 + (lane >> 2);
        int k = kk * 16 + (lane & 3) * 2 + (w & 1) * 8;
        uint32_t v = pack2h(W[k * 64 + n], W[(k + 1) * 64 + n]);
        ((uint32_t*)g_w1frag)[(((size_t)r * 8 + kk) * 128 + q * 32 + lane) * 4 + w] = v;
    }
}

// ======================= shared mma machinery ==============================
// GEMM1: warp (wm1 = wid&3, wn1 = wid>>2); tile m32 x n64; acc[2][8][4].
// GEMM2: warp wid owns m16 rows, all n64; acc2[8][4]. B always from gmem.
__device__ __forceinline__ void two_layer_mma(
    char* smem, uint32_t smem_base, int rel, int lane, int wid,
    uint32_t xoff, float (&acc2)[8][4])
{
    const float* sb0 = (const float*)(smem + OFF_B0);
    const int wm1 = wid & 3;
    const int wn1 = wid >> 2;

    // ---- GEMM1 ----
    float acc[2][8][4];
    #pragma unroll
    for (int i = 0; i < 2; i++)
        #pragma unroll
        for (int j = 0; j < 8; j++)
            #pragma unroll
            for (int q = 0; q < 4; q++) acc[i][j][q] = 0.f;

    {
        const uint32_t Ab = smem_base + xoff;
        const uint4* w0p = g_w0frag + ((size_t)(rel * 2 + wn1) * 8) * 128 + lane;
        #pragma unroll
        for (int kk = 0; kk < 8; kk++) {
            uint4 bq[4];
            #pragma unroll
            for (int q = 0; q < 4; q++) bq[q] = w0p[kk * 128 + q * 32];
            const int chunk = kk * 2 + (lane >> 4);
            uint32_t af[2][4];
            #pragma unroll
            for (int i = 0; i < 2; i++) {
                int row = wm1 * 32 + i * 16 + (lane & 15);
                ldsm_x4(af[i][0], af[i][1], af[i][2], af[i][3],
                        Ab + sw_off(row, chunk));
            }
            #pragma unroll
            for (int i = 0; i < 2; i++)
                #pragma unroll
                for (int j = 0; j < 8; j++)
                    mma_f16(acc[i][j], af[i],
                            (j & 1) ? bq[j >> 1].z : bq[j >> 1].x,
                            (j & 1) ? bq[j >> 1].w : bq[j >> 1].y);
        }
    }
    __syncthreads();

    // ---- epilogue1: H = lrelu(D + b0) -> fp16 into X region ----
    #pragma unroll
    for (int i = 0; i < 2; i++) {
        int row0 = wm1 * 32 + i * 16 + (lane >> 2);
        #pragma unroll
        for (int j = 0; j < 8; j++) {
            int col = wn1 * 64 + j * 8 + 2 * (lane & 3);
            float bv0 = sb0[col], bv1 = sb0[col + 1];
            uint32_t h0 = pack2h(lrelu(acc[i][j][0] + bv0), lrelu(acc[i][j][1] + bv1));
            uint32_t h1 = pack2h(lrelu(acc[i][j][2] + bv0), lrelu(acc[i][j][3] + bv1));
            uint32_t o0 = sw_off(row0, col >> 3) + ((2 * col) & 15);
            uint32_t o1 = sw_off(row0 + 8, col >> 3) + ((2 * col) & 15);
            *(uint32_t*)(smem + xoff + o0) = h0;
            *(uint32_t*)(smem + xoff + o1) = h1;
        }
    }
    __syncthreads();

    // ---- GEMM2 ----
    #pragma unroll
    for (int j = 0; j < 8; j++)
        #pragma unroll
        for (int q = 0; q < 4; q++) acc2[j][q] = 0.f;

    {
        const uint32_t Ab = smem_base + xoff;
        const uint4* w1p = g_w1frag + (size_t)rel * 8 * 128 + lane;
        #pragma unroll
        for (int kk = 0; kk < 8; kk++) {
            uint4 bq[4];
            #pragma unroll
            for (int q = 0; q < 4; q++) bq[q] = w1p[kk * 128 + q * 32];
            const int chunk = kk * 2 + (lane >> 4);
            uint32_t af[4];
            {
                int row = wid * 16 + (lane & 15);
                ldsm_x4(af[0], af[1], af[2], af[3], Ab + sw_off(row, chunk));
            }
            #pragma unroll
            for (int j = 0; j < 8; j++)
                mma_f16(acc2[j], af,
                        (j & 1) ? bq[j >> 1].z : bq[j >> 1].x,
                        (j & 1) ? bq[j >> 1].w : bq[j >> 1].y);
        }
    }
}

__device__ __forceinline__ void load_bias(char* smem, int tid,
                                          const float* b0, const float* b1) {
    if (tid < 128) ((float*)(smem + OFF_B0))[tid] = b0[tid];
    if (tid < 64)  ((float*)(smem + OFF_B1))[tid] = b1[tid];
}

// ======================= UI branch + scatter (fused) =======================
__global__ void __launch_bounds__(256, 2) ui_scatter_kernel(
    const float* __restrict__ u, const float* __restrict__ iv,
    const float* __restrict__ b0, const float* __restrict__ b1,
    const int* __restrict__ s_raw)
{
    extern __shared__ char smem[];
    const int tid = threadIdx.x;

    if (blockIdx.x >= 64) {
        // ---- scatter path (warp-aggregated bucket sort) ----
        __shared__ int sIs64;
        if (tid == 0) {
            int nz = 0;
            #pragma unroll
            for (int i = 1; i < 256; i += 2) nz |= s_raw[i];
            sIs64 = (nz == 0) ? 1 : 0;
        }
        __syncthreads();
        int idx = (blockIdx.x - 64) * 256 + tid;
        int lane = tid & 31;
        int r = sIs64 ? s_raw[2 * idx] : s_raw[idx];
        unsigned m0 = __ballot_sync(0xffffffffu, r == 0);
        unsigned m1 = __ballot_sync(0xffffffffu, r == 1);
        unsigned mine = (r == 0) ? m0 : (r == 1) ? m1 : ~(m0 | m1);
        int leader = __ffs(mine) - 1;
        int base = 0;
        if (lane == leader) base = atomicAdd(&g_pos[r], __popc(mine));
        base = __shfl_sync(0xffffffffu, base, leader);
        g_perm[base + __popc(mine & ((1u << lane) - 1u))] = idx;
        return;
    }

    // ---- UI path ----
    const uint32_t smem_base = smem_to_u32(smem);
    const int lane = tid & 31;
    const int wid = tid >> 5;
    const int rowbase = blockIdx.x * 128;

    load_bias(smem, tid, b0, b1);
    {
        const int xrow = tid >> 1;
        const int half = tid & 1;
        const float* src = (half ? iv : u) + (size_t)(rowbase + xrow) * 64;
        #pragma unroll
        for (int j = 0; j < 8; j++) {
            float4 v0 = ((const float4*)src)[2 * j];
            float4 v1 = ((const float4*)src)[2 * j + 1];
            uint32_t off = sw_off(xrow, half * 8 + j);
            *(uint4*)(smem + OFF_X1 + off) = make_uint4(
                pack2h(v0.x, v0.y), pack2h(v0.z, v0.w),
                pack2h(v1.x, v1.y), pack2h(v1.z, v1.w));
        }
    }
    __syncthreads();

    float acc2[8][4];
    two_layer_mma(smem, smem_base, 3, lane, wid, OFF_X1, acc2);

    // epilogue: g_ui = lrelu(D2 + b1) straight from fragments
    const float* sb1 = (const float*)(smem + OFF_B1);
    int row0 = wid * 16 + (lane >> 2);
    #pragma unroll
    for (int j = 0; j < 8; j++) {
        int col = j * 8 + 2 * (lane & 3);
        float bv0 = sb1[col], bv1 = sb1[col + 1];
        *(float2*)&g_ui[(size_t)(rowbase + row0) * 64 + col] =
            make_float2(lrelu(acc2[j][0] + bv0), lrelu(acc2[j][1] + bv1));
        *(float2*)&g_ui[(size_t)(rowbase + row0 + 8) * 64 + col] =
            make_float2(lrelu(acc2[j][2] + bv0), lrelu(acc2[j][3] + bv1));
    }
}

// ======================= AO branch: 256 rows per CTA =======================
// R8-style grid: 3*TOT/256 CTAs, empty tails exit immediately.
__global__ void __launch_bounds__(256, 2) ao_mma_kernel(
    const float* __restrict__ a, const float* __restrict__ o,
    const float* __restrict__ b0, const float* __restrict__ b1,
    float* __restrict__ out)
{
    extern __shared__ char smem[];
    const uint32_t smem_base = smem_to_u32(smem);
    const int tid = threadIdx.x;
    const int lane = tid & 31;
    const int wid = tid >> 5;
    const int slotbase = blockIdx.x * 256;      // absolute in [0, 3*TOT)
    const int r = slotbase >> 18;               // TOT = 2^18
    const int local = slotbase & (TOT - 1);
    const int count = g_pos[r] - r * TOT;
    if (local >= count) return;
    const int nvalid = min(256, count - local);

    load_bias(smem, tid, b0 + r * 128, b1 + r * 64);

    // gather X for both blocks: thread = half a row of each block
    {
        const int xrow = tid >> 1;
        const int half = tid & 1;
        #pragma unroll
        for (int bi = 0; bi < 2; bi++) {
            uint32_t xoff = bi ? OFF_X2 : OFF_X1;
            if (bi * 128 + xrow < nvalid) {
                const int grow = g_perm[slotbase + bi * 128 + xrow];
                const float* src = (half ? o : a) + (size_t)grow * 64;
                #pragma unroll
                for (int j = 0; j < 8; j++) {
                    float4 v0 = ((const float4*)src)[2 * j];
                    float4 v1 = ((const float4*)src)[2 * j + 1];
                    uint32_t off = sw_off(xrow, half * 8 + j);
                    *(uint4*)(smem + xoff + off) = make_uint4(
                        pack2h(v0.x, v0.y), pack2h(v0.z, v0.w),
                        pack2h(v1.x, v1.y), pack2h(v1.z, v1.w));
                }
            } else {
                #pragma unroll
                for (int j = 0; j < 8; j++)
                    *(uint4*)(smem + xoff + sw_off(xrow, half * 8 + j)) =
                        make_uint4(0, 0, 0, 0);
            }
        }
    }
    __syncthreads();

    const float* sb1 = (const float*)(smem + OFF_B1);

    #pragma unroll 1
    for (int bi = 0; bi < 2; bi++) {
        if (bi * 128 >= nvalid) break;
        const uint32_t xoff = bi ? OFF_X2 : OFF_X1;
        float acc2[8][4];
        two_layer_mma(smem, smem_base, r, lane, wid, xoff, acc2);
        __syncthreads();

        // epilogue2: stage D2 (stride 68) into this block's own X region
        // (H dead after GEMM2; X + 2K pad = 34816 B fits exactly).
        float* sD2 = (float*)(smem + xoff);
        {
            int row0 = wid * 16 + (lane >> 2);
            #pragma unroll
            for (int j = 0; j < 8; j++) {
                int col = j * 8 + 2 * (lane & 3);
                *(float2*)&sD2[row0 * 68 + col] =
                    make_float2(acc2[j][0], acc2[j][1]);
                *(float2*)&sD2[(row0 + 8) * 68 + col] =
                    make_float2(acc2[j][2], acc2[j][3]);
            }
        }
        __syncthreads();

        if (tid < 128 && bi * 128 + tid < nvalid) {
            int grow = g_perm[slotbase + bi * 128 + tid];
            const float4* uir = (const float4*)(g_ui + (size_t)(grow >> 5) * 64);
            const float* drow = sD2 + tid * 68;
            float sdot = 0.f;
            #pragma unroll
            for (int c4 = 0; c4 < 16; c4++) {
                float4 uv = uir[c4];
                float v0 = lrelu(drow[4 * c4 + 0] + sb1[4 * c4 + 0]);
                float v1 = lrelu(drow[4 * c4 + 1] + sb1[4 * c4 + 1]);
                float v2 = lrelu(drow[4 * c4 + 2] + sb1[4 * c4 + 2]);
                float v3 = lrelu(drow[4 * c4 + 3] + sb1[4 * c4 + 3]);
                sdot = fmaf(v0, uv.x, sdot); sdot = fmaf(v1, uv.y, sdot);
                sdot = fmaf(v2, uv.z, sdot); sdot = fmaf(v3, uv.w, sdot);
            }
            out[grow] = sdot;
        }
        __syncthreads();
    }
}

// ===========================================================================
extern "C" void kernel_launch(void* const* d_in, const int* in_sizes, int n_in,
                              void* d_out, int out_size) {
    const float* u    = (const float*)d_in[0];
    const float* iv   = (const float*)d_in[1];
    const float* a    = (const float*)d_in[2];
    const float* o    = (const float*)d_in[3];
    const int*   s    = (const int*)  d_in[4];
    const float* aoW0 = (const float*)d_in[5];
    const float* aob0 = (const float*)d_in[6];
    const float* aoW1 = (const float*)d_in[7];
    const float* aob1 = (const float*)d_in[8];
    const float* uiW0 = (const float*)d_in[9];
    const float* uib0 = (const float*)d_in[10];
    const float* uiW1 = (const float*)d_in[11];
    const float* uib1 = (const float*)d_in[12];
    float* out = (float*)d_out;

    cudaFuncSetAttribute((const void*)ui_scatter_kernel,
                         cudaFuncAttributeMaxDynamicSharedMemorySize, SM_UI);
    cudaFuncSetAttribute((const void*)ao_mma_kernel,
                         cudaFuncAttributeMaxDynamicSharedMemorySize, SM_AO);

    prep_w_kernel<<<192, 256>>>(aoW0, aoW1, uiW0, uiW1);
    ui_scatter_kernel<<<64 + TOT / 256, 256, SM_UI>>>(u, iv, uib0, uib1, s);
    ao_mma_kernel<<<3 * TOT / 256, 256, SM_AO>>>(a, o, aob0, aob1, out);
}

// round 13
// speedup vs baseline: 1.2751x; 1.0772x over previous
#include <cuda_runtime.h>
#include <cuda_fp16.h>
#include <cstdint>

// Model_53283364274775 on GB300 (plain sm_103 PTX target -> no tcgen05):
// single-pass fp16 mma.sync. R13: register-resident H. GEMM1 m16n128/warp
// (two n64 passes); H = lrelu(D+b0) packed in-register as GEMM2 A-fragments
// (D-fragment layout == A-fragment layout). No epi1 smem round-trip, no
// GEMM2 A-ldmatrix, 3 barriers/block. All weights as gmem B-fragments
// (35KB smem -> L1D caches the 144KB fragment images).

#define B_   8192
#define N_   32
#define TOT  (B_ * N_)          // 262144 = 2^18
#define SLOPE 0.01f

__device__ int   g_pos[3];
__device__ int   g_perm[3 * TOT];
__device__ float g_ui[B_ * 64];
// W0 B-fragments: [rel][kk(8)][j2(8)][lane] uint4  (32KB/rel)
__device__ uint4 g_w0frag[4 * 8 * 8 * 32];
// W1 B-fragments: [rel][kk(8)][q(4)][lane] uint4   (16KB/rel)
__device__ uint4 g_w1frag[4 * 8 * 4 * 32];

__device__ __forceinline__ float lrelu(float x) { return x >= 0.f ? x : SLOPE * x; }

__device__ __forceinline__ uint32_t smem_to_u32(const void* p) {
    uint32_t a;
    asm("{ .reg .u64 t; cvta.to.shared.u64 t, %1; cvt.u32.u64 %0, t; }"
        : "=r"(a) : "l"(p));
    return a;
}
__device__ __forceinline__ void ldsm_x4(uint32_t& r0, uint32_t& r1,
                                        uint32_t& r2, uint32_t& r3, uint32_t addr) {
    asm volatile("ldmatrix.sync.aligned.m8n8.x4.shared.b16 {%0,%1,%2,%3}, [%4];"
        : "=r"(r0), "=r"(r1), "=r"(r2), "=r"(r3) : "r"(addr));
}
__device__ __forceinline__ void mma_f16(float* d, const uint32_t* a4,
                                        uint32_t b0, uint32_t b1) {
    asm volatile("mma.sync.aligned.m16n8k16.row.col.f32.f16.f16.f32 "
        "{%0,%1,%2,%3}, {%4,%5,%6,%7}, {%8,%9}, {%0,%1,%2,%3};"
        : "+f"(d[0]), "+f"(d[1]), "+f"(d[2]), "+f"(d[3])
        : "r"(a4[0]), "r"(a4[1]), "r"(a4[2]), "r"(a4[3]), "r"(b0), "r"(b1));
}
// 256B rows of fp16, XOR swizzle on 16B chunks: conflict-free ldmatrix
__device__ __forceinline__ uint32_t sw_off(int row, int chunk16) {
    return (uint32_t)(row * 256 + ((chunk16 ^ (row & 7)) << 4));
}
__device__ __forceinline__ uint32_t pack2h(float f0, float f1) {
    return (uint32_t)__half_as_ushort(__float2half_rn(f0)) |
           ((uint32_t)__half_as_ushort(__float2half_rn(f1)) << 16);
}

// smem layout (bytes): b0 @0 (512) | b1 @512 (256) | pad | X @1024 (32K+2K)
// D2 staging (34816B) reuses the X region after GEMM2.
#define OFF_B0   0
#define OFF_B1   512
#define OFF_X    1024
#define SM_BYTES 35840

// ======================= prep_w (+ g_pos init) =============================
__global__ void prep_w_kernel(const float* __restrict__ aoW0,
                              const float* __restrict__ aoW1,
                              const float* __restrict__ uiW0,
                              const float* __restrict__ uiW1) {
    int idx = blockIdx.x * blockDim.x + threadIdx.x;   // 0..49151
    if (blockIdx.x == 0 && threadIdx.x < 3)
        g_pos[threadIdx.x] = threadIdx.x * TOT;

    if (idx < 32768) {
        // W0 frag word: (((rel*8+kk)*8 + j2)*32 + lane)*4 + w
        int r = idx >> 13, t = idx & 8191;
        int w    = t & 3;
        int lane = (t >> 2) & 31;
        int j2   = (t >> 7) & 7;
        int kk   = (t >> 10) & 7;
        const float* W = (r < 3) ? (aoW0 + r * 16384) : uiW0;
        int j = 2 * j2 + (w >> 1);
        int n = j * 8 + (lane >> 2);
        int k = kk * 16 + (lane & 3) * 2 + (w & 1) * 8;
        uint32_t v = pack2h(W[k * 128 + n], W[(k + 1) * 128 + n]);
        ((uint32_t*)g_w0frag)[((((size_t)r * 8 + kk) * 8 + j2) * 32 + lane) * 4 + w] = v;
    } else if (idx < 49152) {
        // W1 frag word: (((rel*8+kk)*4 + q)*32 + lane)*4 + w
        int t2 = idx - 32768;
        int r = t2 >> 12, t = t2 & 4095;
        int w    = t & 3;
        int lane = (t >> 2) & 31;
        int q    = (t >> 7) & 3;
        int kk   = (t >> 9) & 7;
        const float* W = (r < 3) ? (aoW1 + r * 8192) : uiW1;
        int j = 2 * q + (w >> 1);
        int n = j * 8 + (lane >> 2);
        int k = kk * 16 + (lane & 3) * 2 + (w & 1) * 8;
        uint32_t v = pack2h(W[k * 64 + n], W[(k + 1) * 64 + n]);
        ((uint32_t*)g_w1frag)[((((size_t)r * 8 + kk) * 4 + q) * 32 + lane) * 4 + w] = v;
    }
}

// ======================= core: two layers, register H ======================
// Warp wid owns rows 16*wid..+15. GEMM1 in two n64 halves (acc 32 regs),
// converts each half's D directly into GEMM2 A-fragments (afrag2[8][4]).
// GEMM2 accumulates acc2[8][4] over H-chunks c=0..7 (ascending: same
// accumulation order as the smem-round-trip version -> bitwise identical).
__device__ __forceinline__ void two_layer_reg(
    char* smem, uint32_t smem_base, int rel, int lane, int wid,
    float (&acc2)[8][4])
{
    const float* sb0 = (const float*)(smem + OFF_B0);
    uint32_t afrag2[8][4];
    const uint32_t Ab = smem_base + OFF_X;
    const int arow = wid * 16 + (lane & 15);

    #pragma unroll
    for (int h = 0; h < 2; h++) {
        float acc[8][4];
        #pragma unroll
        for (int j = 0; j < 8; j++)
            #pragma unroll
            for (int q = 0; q < 4; q++) acc[j][q] = 0.f;

        const uint4* w0p = g_w0frag + (((size_t)rel * 8) * 8 + h * 4) * 32 + lane;
        #pragma unroll
        for (int kk = 0; kk < 8; kk++) {
            uint4 bq[4];
            #pragma unroll
            for (int q = 0; q < 4; q++) bq[q] = w0p[(kk * 8 + q) * 32];
            uint32_t af[4];
            ldsm_x4(af[0], af[1], af[2], af[3],
                    Ab + sw_off(arow, kk * 2 + (lane >> 4)));
            #pragma unroll
            for (int j = 0; j < 8; j++)
                mma_f16(acc[j], af,
                        (j & 1) ? bq[j >> 1].z : bq[j >> 1].x,
                        (j & 1) ? bq[j >> 1].w : bq[j >> 1].y);
        }

        // D -> bias+lrelu -> fp16 A-fragments for GEMM2 (in registers)
        #pragma unroll
        for (int q2 = 0; q2 < 4; q2++) {
            int c0 = h * 64 + q2 * 16 + 2 * (lane & 3);      // tile 2q2 cols
            float b00 = sb0[c0],     b01 = sb0[c0 + 1];
            float b80 = sb0[c0 + 8], b81 = sb0[c0 + 9];      // tile 2q2+1 cols
            afrag2[h * 4 + q2][0] =
                pack2h(lrelu(acc[2 * q2][0] + b00), lrelu(acc[2 * q2][1] + b01));
            afrag2[h * 4 + q2][1] =
                pack2h(lrelu(acc[2 * q2][2] + b00), lrelu(acc[2 * q2][3] + b01));
            afrag2[h * 4 + q2][2] =
                pack2h(lrelu(acc[2 * q2 + 1][0] + b80), lrelu(acc[2 * q2 + 1][1] + b81));
            afrag2[h * 4 + q2][3] =
                pack2h(lrelu(acc[2 * q2 + 1][2] + b80), lrelu(acc[2 * q2 + 1][3] + b81));
        }
    }

    // ---- GEMM2: acc2 = H @ W1^T ----
    #pragma unroll
    for (int j = 0; j < 8; j++)
        #pragma unroll
        for (int q = 0; q < 4; q++) acc2[j][q] = 0.f;

    const uint4* w1p = g_w1frag + ((size_t)rel * 8) * 4 * 32 + lane;
    #pragma unroll
    for (int c = 0; c < 8; c++) {
        uint4 bq[4];
        #pragma unroll
        for (int q = 0; q < 4; q++) bq[q] = w1p[(c * 4 + q) * 32];
        #pragma unroll
        for (int j = 0; j < 8; j++)
            mma_f16(acc2[j], afrag2[c],
                    (j & 1) ? bq[j >> 1].z : bq[j >> 1].x,
                    (j & 1) ? bq[j >> 1].w : bq[j >> 1].y);
    }
}

__device__ __forceinline__ void load_bias(char* smem, int tid,
                                          const float* b0, const float* b1) {
    if (tid < 128) ((float*)(smem + OFF_B0))[tid] = b0[tid];
    if (tid < 64)  ((float*)(smem + OFF_B1))[tid] = b1[tid];
}

// ======================= UI branch + scatter (fused) =======================
__global__ void __launch_bounds__(256, 2) ui_scatter_kernel(
    const float* __restrict__ u, const float* __restrict__ iv,
    const float* __restrict__ b0, const float* __restrict__ b1,
    const int* __restrict__ s_raw)
{
    extern __shared__ char smem[];
    const int tid = threadIdx.x;

    if (blockIdx.x >= 64) {
        // ---- scatter path (warp-aggregated bucket sort) ----
        __shared__ int sIs64;
        if (tid == 0) {
            int nz = 0;
            #pragma unroll
            for (int i = 1; i < 256; i += 2) nz |= s_raw[i];
            sIs64 = (nz == 0) ? 1 : 0;
        }
        __syncthreads();
        int idx = (blockIdx.x - 64) * 256 + tid;
        int lane = tid & 31;
        int r = sIs64 ? s_raw[2 * idx] : s_raw[idx];
        unsigned m0 = __ballot_sync(0xffffffffu, r == 0);
        unsigned m1 = __ballot_sync(0xffffffffu, r == 1);
        unsigned mine = (r == 0) ? m0 : (r == 1) ? m1 : ~(m0 | m1);
        int leader = __ffs(mine) - 1;
        int base = 0;
        if (lane == leader) base = atomicAdd(&g_pos[r], __popc(mine));
        base = __shfl_sync(0xffffffffu, base, leader);
        g_perm[base + __popc(mine & ((1u << lane) - 1u))] = idx;
        return;
    }

    // ---- UI path ----
    const uint32_t smem_base = smem_to_u32(smem);
    const int lane = tid & 31;
    const int wid = tid >> 5;
    const int rowbase = blockIdx.x * 128;

    load_bias(smem, tid, b0, b1);
    {
        const int xrow = tid >> 1;
        const int half = tid & 1;
        const float* src = (half ? iv : u) + (size_t)(rowbase + xrow) * 64;
        #pragma unroll
        for (int j = 0; j < 8; j++) {
            float4 v0 = ((const float4*)src)[2 * j];
            float4 v1 = ((const float4*)src)[2 * j + 1];
            uint32_t off = sw_off(xrow, half * 8 + j);
            *(uint4*)(smem + OFF_X + off) = make_uint4(
                pack2h(v0.x, v0.y), pack2h(v0.z, v0.w),
                pack2h(v1.x, v1.y), pack2h(v1.z, v1.w));
        }
    }
    __syncthreads();

    float acc2[8][4];
    two_layer_reg(smem, smem_base, 3, lane, wid, acc2);

    // epilogue: g_ui = lrelu(D2 + b1) straight from fragments
    const float* sb1 = (const float*)(smem + OFF_B1);
    int row0 = wid * 16 + (lane >> 2);
    #pragma unroll
    for (int j = 0; j < 8; j++) {
        int col = j * 8 + 2 * (lane & 3);
        float bv0 = sb1[col], bv1 = sb1[col + 1];
        *(float2*)&g_ui[(size_t)(rowbase + row0) * 64 + col] =
            make_float2(lrelu(acc2[j][0] + bv0), lrelu(acc2[j][1] + bv1));
        *(float2*)&g_ui[(size_t)(rowbase + row0 + 8) * 64 + col] =
            make_float2(lrelu(acc2[j][2] + bv0), lrelu(acc2[j][3] + bv1));
    }
}

// ======================= AO branch: 128 rows per CTA =======================
// 3*TOT/128 = 6144 CTAs; empty tails exit immediately. 3 barriers total.
__global__ void __launch_bounds__(256, 2) ao_mma_kernel(
    const float* __restrict__ a, const float* __restrict__ o,
    const float* __restrict__ b0, const float* __restrict__ b1,
    float* __restrict__ out)
{
    extern __shared__ char smem[];
    const uint32_t smem_base = smem_to_u32(smem);
    const int tid = threadIdx.x;
    const int lane = tid & 31;
    const int wid = tid >> 5;
    const int slotbase = blockIdx.x * 128;      // absolute in [0, 3*TOT)
    const int r = slotbase >> 18;               // TOT = 2^18
    const int local = slotbase & (TOT - 1);
    const int count = g_pos[r] - r * TOT;
    if (local >= count) return;
    const int nvalid = min(128, count - local);

    load_bias(smem, tid, b0 + r * 128, b1 + r * 64);

    // gather X: thread = half a row (half 0 = a, half 1 = o)
    {
        const int xrow = tid >> 1;
        const int half = tid & 1;
        if (xrow < nvalid) {
            const int grow = g_perm[slotbase + xrow];
            const float* src = (half ? o : a) + (size_t)grow * 64;
            #pragma unroll
            for (int j = 0; j < 8; j++) {
                float4 v0 = ((const float4*)src)[2 * j];
                float4 v1 = ((const float4*)src)[2 * j + 1];
                uint32_t off = sw_off(xrow, half * 8 + j);
                *(uint4*)(smem + OFF_X + off) = make_uint4(
                    pack2h(v0.x, v0.y), pack2h(v0.z, v0.w),
                    pack2h(v1.x, v1.y), pack2h(v1.z, v1.w));
            }
        } else {
            #pragma unroll
            for (int j = 0; j < 8; j++)
                *(uint4*)(smem + OFF_X + sw_off(xrow, half * 8 + j)) =
                    make_uint4(0, 0, 0, 0);
        }
    }
    __syncthreads();

    float acc2[8][4];
    two_layer_reg(smem, smem_base, r, lane, wid, acc2);
    __syncthreads();        // all warps done reading X before D2 staging

    // stage D2 (stride 68) into the dead X region
    float* sD2 = (float*)(smem + OFF_X);
    {
        int row0 = wid * 16 + (lane >> 2);
        #pragma unroll
        for (int j = 0; j < 8; j++) {
            int col = j * 8 + 2 * (lane & 3);
            *(float2*)&sD2[row0 * 68 + col] =
                make_float2(acc2[j][0], acc2[j][1]);
            *(float2*)&sD2[(row0 + 8) * 68 + col] =
                make_float2(acc2[j][2], acc2[j][3]);
        }
    }
    __syncthreads();

    const float* sb1 = (const float*)(smem + OFF_B1);
    if (tid < nvalid) {
        int grow = g_perm[slotbase + tid];
        const float4* uir = (const float4*)(g_ui + (size_t)(grow >> 5) * 64);
        const float* drow = sD2 + tid * 68;
        float sdot = 0.f;
        #pragma unroll
        for (int c4 = 0; c4 < 16; c4++) {
            float4 uv = uir[c4];
            float v0 = lrelu(drow[4 * c4 + 0] + sb1[4 * c4 + 0]);
            float v1 = lrelu(drow[4 * c4 + 1] + sb1[4 * c4 + 1]);
            float v2 = lrelu(drow[4 * c4 + 2] + sb1[4 * c4 + 2]);
            float v3 = lrelu(drow[4 * c4 + 3] + sb1[4 * c4 + 3]);
            sdot = fmaf(v0, uv.x, sdot); sdot = fmaf(v1, uv.y, sdot);
            sdot = fmaf(v2, uv.z, sdot); sdot = fmaf(v3, uv.w, sdot);
        }
        out[grow] = sdot;
    }
}

// ===========================================================================
extern "C" void kernel_launch(void* const* d_in, const int* in_sizes, int n_in,
                              void* d_out, int out_size) {
    const float* u    = (const float*)d_in[0];
    const float* iv   = (const float*)d_in[1];
    const float* a    = (const float*)d_in[2];
    const float* o    = (const float*)d_in[3];
    const int*   s    = (const int*)  d_in[4];
    const float* aoW0 = (const float*)d_in[5];
    const float* aob0 = (const float*)d_in[6];
    const float* aoW1 = (const float*)d_in[7];
    const float* aob1 = (const float*)d_in[8];
    const float* uiW0 = (const float*)d_in[9];
    const float* uib0 = (const float*)d_in[10];
    const float* uiW1 = (const float*)d_in[11];
    const float* uib1 = (const float*)d_in[12];
    float* out = (float*)d_out;

    cudaFuncSetAttribute((const void*)ui_scatter_kernel,
                         cudaFuncAttributeMaxDynamicSharedMemorySize, SM_BYTES);
    cudaFuncSetAttribute((const void*)ao_mma_kernel,
                         cudaFuncAttributeMaxDynamicSharedMemorySize, SM_BYTES);

    prep_w_kernel<<<192, 256>>>(aoW0, aoW1, uiW0, uiW1);
    ui_scatter_kernel<<<64 + TOT / 256, 256, SM_BYTES>>>(u, iv, uib0, uib1, s);
    ao_mma_kernel<<<3 * TOT / 128, 256, SM_BYTES>>>(a, o, aob0, aob1, out);
}